// round 3
// baseline (speedup 1.0000x reference)
#include <cuda_runtime.h>

// Problem constants
#define B 32
#define S 2048
#define H 1024

// ---- split-softmax config ----
#define NSPLIT 64            // S-splits per batch
#define CH (S / NSPLIT)      // 32 rows per CTA
#define TROWS 8              // rows per SMEM tile
#define NTILES (CH / TROWS)  // 4

// ---- q GEMV config ----
#define KSLICES 32
#define KCH (H / KSLICES)    // 32
#define BG 4                 // batches per q-block

// Scratch (no cudaMalloc allowed)
__device__ float  g_qpart[KSLICES * B * H];          // 4 MB
__device__ float  g_q[B * H];                        // 128 KB
__device__ float4 g_pacc[B * NSPLIT * (H / 4)];      // 8 MB
__device__ float  g_ml[B * NSPLIT * 2];

// ---------------------------------------------------------------------------
// cp.async helpers
// ---------------------------------------------------------------------------
__device__ __forceinline__ unsigned smem_u32(const void* p) {
    return (unsigned)__cvta_generic_to_shared(p);
}
__device__ __forceinline__ void cp_async16(unsigned dst, const void* src) {
    asm volatile("cp.async.cg.shared.global [%0], [%1], 16;\n"
                 :: "r"(dst), "l"(src));
}
__device__ __forceinline__ void cp_commit() {
    asm volatile("cp.async.commit_group;\n" ::: "memory");
}
template <int N>
__device__ __forceinline__ void cp_wait() {
    asm volatile("cp.async.wait_group %0;\n" :: "n"(N) : "memory");
}

// ---------------------------------------------------------------------------
// Kernel 1: partial q[b,h] = sum_{k in slice} h_t[b,k] * W[k,h]
// grid (1, KSLICES=32, B/BG=8), 256 threads.
// Thread owns 4 consecutive h (float4 W loads), BG batch accumulators.
// KCH=32 independent LDG.128 per thread -> 512 B in flight per thread.
// ---------------------------------------------------------------------------
__global__ __launch_bounds__(256) void qpart_kernel(const float* __restrict__ h_t,
                                                    const float* __restrict__ W)
{
    __shared__ float hs[BG][KCH];
    const int tid = threadIdx.x;
    const int k0  = blockIdx.y * KCH;
    const int bg  = blockIdx.z;

    // load h_t slice: BG*KCH = 128 floats
    if (tid < BG * KCH) {
        int j  = tid / KCH;
        int kk = tid % KCH;
        hs[j][kk] = h_t[(bg * BG + j) * H + k0 + kk];
    }
    __syncthreads();

    float4 acc[BG];
    #pragma unroll
    for (int j = 0; j < BG; j++) acc[j] = make_float4(0.f, 0.f, 0.f, 0.f);

    const float4* wp = reinterpret_cast<const float4*>(W) + (size_t)k0 * 256 + tid;
    #pragma unroll
    for (int kk = 0; kk < KCH; kk++) {
        float4 w = wp[(size_t)kk * 256];
        #pragma unroll
        for (int j = 0; j < BG; j++) {
            float h = hs[j][kk];
            acc[j].x = fmaf(h, w.x, acc[j].x);
            acc[j].y = fmaf(h, w.y, acc[j].y);
            acc[j].z = fmaf(h, w.z, acc[j].z);
            acc[j].w = fmaf(h, w.w, acc[j].w);
        }
    }
    float4* qp = reinterpret_cast<float4*>(g_qpart);
    #pragma unroll
    for (int j = 0; j < BG; j++)
        qp[((size_t)blockIdx.y * B + bg * BG + j) * 256 + tid] = acc[j];
}

// ---------------------------------------------------------------------------
// Kernel 1b: q[b,h] = sum over KSLICES partials. grid (128), 256 threads.
// ---------------------------------------------------------------------------
__global__ __launch_bounds__(256) void qreduce_kernel()
{
    const int idx = blockIdx.x * 256 + threadIdx.x;   // 0 .. B*H-1
    float v = 0.f;
    #pragma unroll
    for (int p = 0; p < KSLICES; p++)
        v += g_qpart[(size_t)p * (B * H) + idx];
    g_q[idx] = v;
}

// ---------------------------------------------------------------------------
// Kernel 2: per-(b, split) online-softmax weighted sum over CH rows of cntx,
// cp.async double-buffered. grid (NSPLIT, B), 256 threads.
// dyn smem: q[1024] + 2 * TROWS*1024 + scores[TROWS]  (~68 KB)
// ---------------------------------------------------------------------------
#define SMEM_FLOATS (H + 2 * TROWS * H + TROWS)

__global__ __launch_bounds__(256) void split_kernel(const float* __restrict__ cntx)
{
    extern __shared__ float sm[];
    float* q_s    = sm;                      // 1024
    float* bufs   = sm + H;                  // 2 * TROWS*1024
    float* scores = sm + H + 2 * TROWS * H;  // TROWS
    float4* q_s4  = reinterpret_cast<float4*>(q_s);
    const float4* q4 = reinterpret_cast<const float4*>(q_s);

    const int tid  = threadIdx.x;
    const int b    = blockIdx.y;
    const int sp   = blockIdx.x;
    const int wid  = tid >> 5;
    const int lane = tid & 31;

    const float* base = cntx + ((size_t)b * S + (size_t)sp * CH) * H;

    // issue tile t into buffer buf (8 rows x 1024 floats, 16B per cp.async)
    auto issue = [&](int t, int buf) {
        const char* src = (const char*)(base + (size_t)t * TROWS * H) + tid * 16;
        unsigned dst = smem_u32(bufs) + (unsigned)buf * (TROWS * H * 4) + tid * 16;
        #pragma unroll
        for (int i = 0; i < TROWS; i++)
            cp_async16(dst + i * (H * 4), src + i * (size_t)(H * 4));
        cp_commit();
    };

    issue(0, 0);
    issue(1, 1);

    // q[b,:] — one float4 per thread from precomputed g_q
    q_s4[tid] = reinterpret_cast<const float4*>(g_q)[b * 256 + tid];

    float m = -1e30f, l = 0.f;
    float4 acc = make_float4(0.f, 0.f, 0.f, 0.f);

    #pragma unroll
    for (int t = 0; t < NTILES; t++) {
        if (t + 1 < NTILES) cp_wait<1>(); else cp_wait<0>();
        __syncthreads();

        const float4* t4 = reinterpret_cast<const float4*>(
            bufs + (size_t)(t & 1) * (TROWS * H));

        // scores: warp wid handles row wid
        {
            float p = 0.f;
            #pragma unroll
            for (int j = 0; j < 8; j++) {
                float4 v  = t4[wid * 256 + lane + 32 * j];
                float4 qv = q4[lane + 32 * j];
                p = fmaf(v.x, qv.x, p);
                p = fmaf(v.y, qv.y, p);
                p = fmaf(v.z, qv.z, p);
                p = fmaf(v.w, qv.w, p);
            }
            #pragma unroll
            for (int off = 16; off > 0; off >>= 1)
                p += __shfl_xor_sync(0xffffffffu, p, off);
            if (lane == 0) scores[wid] = p;
        }
        __syncthreads();

        // online softmax update (all threads identical)
        float mnew = m;
        #pragma unroll
        for (int s = 0; s < TROWS; s++) mnew = fmaxf(mnew, scores[s]);
        float corr = __expf(m - mnew);
        acc.x *= corr; acc.y *= corr; acc.z *= corr; acc.w *= corr;
        l *= corr;
        float w[TROWS];
        #pragma unroll
        for (int s = 0; s < TROWS; s++) {
            w[s] = __expf(scores[s] - mnew);
            l += w[s];
        }
        m = mnew;

        // accumulate weighted rows from the same smem tile
        #pragma unroll
        for (int s = 0; s < TROWS; s++) {
            float4 v = t4[s * 256 + tid];
            acc.x = fmaf(w[s], v.x, acc.x);
            acc.y = fmaf(w[s], v.y, acc.y);
            acc.z = fmaf(w[s], v.z, acc.z);
            acc.w = fmaf(w[s], v.w, acc.w);
        }
        __syncthreads();  // tile + scores fully consumed

        if (t + 2 < NTILES) issue(t + 2, t & 1);
    }

    g_pacc[((size_t)b * NSPLIT + sp) * 256 + tid] = acc;
    if (tid == 0) {
        g_ml[(b * NSPLIT + sp) * 2 + 0] = m;
        g_ml[(b * NSPLIT + sp) * 2 + 1] = l;
    }
}

// ---------------------------------------------------------------------------
// Kernel 3: combine splits + epilogue. grid (B), 256 threads.
// ---------------------------------------------------------------------------
__global__ __launch_bounds__(256) void combine_kernel(const float* __restrict__ h_t,
                                                      const float* __restrict__ alpha,
                                                      const float* __restrict__ beta,
                                                      float* __restrict__ out)
{
    const int tid = threadIdx.x;
    const int b   = blockIdx.x;

    float M = -1e30f;
    #pragma unroll
    for (int i = 0; i < NSPLIT; i++)
        M = fmaxf(M, g_ml[(b * NSPLIT + i) * 2 + 0]);

    float L = 0.f;
    float4 o = make_float4(0.f, 0.f, 0.f, 0.f);
    #pragma unroll 8
    for (int i = 0; i < NSPLIT; i++) {
        float mi = g_ml[(b * NSPLIT + i) * 2 + 0];
        float li = g_ml[(b * NSPLIT + i) * 2 + 1];
        float wi = __expf(mi - M);
        L += li * wi;
        float4 p = g_pacc[((size_t)b * NSPLIT + i) * 256 + tid];
        o.x = fmaf(wi, p.x, o.x);
        o.y = fmaf(wi, p.y, o.y);
        o.z = fmaf(wi, p.z, o.z);
        o.w = fmaf(wi, p.w, o.w);
    }
    float a  = alpha[0];
    float bt = beta[0] / L;
    const float4* ht4 = reinterpret_cast<const float4*>(h_t);
    float4 hv = ht4[b * 256 + tid];
    float4 res;
    res.x = fmaf(a, hv.x, bt * o.x);
    res.y = fmaf(a, hv.y, bt * o.y);
    res.z = fmaf(a, hv.z, bt * o.z);
    res.w = fmaf(a, hv.w, bt * o.w);
    reinterpret_cast<float4*>(out)[b * 256 + tid] = res;
}

// ---------------------------------------------------------------------------
extern "C" void kernel_launch(void* const* d_in, const int* in_sizes, int n_in,
                              void* d_out, int out_size)
{
    const float* h_t   = (const float*)d_in[0];
    const float* cntx  = (const float*)d_in[1];
    const float* W     = (const float*)d_in[2];
    const float* alpha = (const float*)d_in[3];
    const float* beta  = (const float*)d_in[4];
    float* out = (float*)d_out;

    const int smem_bytes = SMEM_FLOATS * (int)sizeof(float); // ~68.2 KB
    cudaFuncSetAttribute(split_kernel,
                         cudaFuncAttributeMaxDynamicSharedMemorySize, smem_bytes);

    qpart_kernel<<<dim3(1, KSLICES, B / BG), 256>>>(h_t, W);
    qreduce_kernel<<<B * H / 256, 256>>>();
    split_kernel<<<dim3(NSPLIT, B), 256, smem_bytes>>>(cntx);
    combine_kernel<<<B, 256>>>(h_t, alpha, beta, out);
}

// round 4
// speedup vs baseline: 1.7395x; 1.7395x over previous
#include <cuda_runtime.h>

// Problem constants
#define B 32
#define S 2048
#define H 1024

// ---- split-softmax config ----
#define NSPLIT 16            // S-splits per batch -> 512 CTAs = 1 wave @ 4 CTA/SM
#define CH (S / NSPLIT)      // 128 rows per CTA
#define TROWS 8              // rows per register tile
#define NTILES (CH / TROWS)  // 16

// ---- q GEMV config ----
#define KSLICES 32
#define KCH (H / KSLICES)    // 32
#define BG 4

// Scratch (no cudaMalloc allowed)
__device__ float  g_qpart[KSLICES * B * H];          // 4 MB
__device__ float  g_q[B * H];                        // 128 KB
__device__ float4 g_pacc[B * NSPLIT * (H / 4)];      // 2 MB
__device__ float  g_ml[B * NSPLIT * 2];

// ---------------------------------------------------------------------------
// Kernel 1: partial q[b,h] = sum_{k in slice} h_t[b,k] * W[k,h]
// grid (1, KSLICES=32, B/BG=8), 256 threads. (unchanged from R3 — fast)
// ---------------------------------------------------------------------------
__global__ __launch_bounds__(256) void qpart_kernel(const float* __restrict__ h_t,
                                                    const float* __restrict__ W)
{
    __shared__ float hs[BG][KCH];
    const int tid = threadIdx.x;
    const int k0  = blockIdx.y * KCH;
    const int bg  = blockIdx.z;

    if (tid < BG * KCH) {
        int j  = tid / KCH;
        int kk = tid % KCH;
        hs[j][kk] = h_t[(bg * BG + j) * H + k0 + kk];
    }
    __syncthreads();

    float4 acc[BG];
    #pragma unroll
    for (int j = 0; j < BG; j++) acc[j] = make_float4(0.f, 0.f, 0.f, 0.f);

    const float4* wp = reinterpret_cast<const float4*>(W) + (size_t)k0 * 256 + tid;
    #pragma unroll
    for (int kk = 0; kk < KCH; kk++) {
        float4 w = wp[(size_t)kk * 256];
        #pragma unroll
        for (int j = 0; j < BG; j++) {
            float h = hs[j][kk];
            acc[j].x = fmaf(h, w.x, acc[j].x);
            acc[j].y = fmaf(h, w.y, acc[j].y);
            acc[j].z = fmaf(h, w.z, acc[j].z);
            acc[j].w = fmaf(h, w.w, acc[j].w);
        }
    }
    float4* qp = reinterpret_cast<float4*>(g_qpart);
    #pragma unroll
    for (int j = 0; j < BG; j++)
        qp[((size_t)blockIdx.y * B + bg * BG + j) * 256 + tid] = acc[j];
}

// ---------------------------------------------------------------------------
// Kernel 1b: q[b,h] = sum over KSLICES partials. grid (128), 256 threads.
// ---------------------------------------------------------------------------
__global__ __launch_bounds__(256) void qreduce_kernel()
{
    const int idx = blockIdx.x * 256 + threadIdx.x;
    float v = 0.f;
    #pragma unroll
    for (int p = 0; p < KSLICES; p++)
        v += g_qpart[(size_t)p * (B * H) + idx];
    g_q[idx] = v;
}

// ---------------------------------------------------------------------------
// Kernel 2: register-tile online-softmax split. grid (NSPLIT, B), 256 thr.
// Each thread: float4 column slice of TROWS rows in REGISTERS.
// SMEM used only for the tiny score reduction (no tile staging).
// ---------------------------------------------------------------------------
__global__ void __launch_bounds__(256, 4) split_kernel(const float* __restrict__ cntx)
{
    __shared__ float red[TROWS * 8];     // [row][warp]
    __shared__ float scores[TROWS];

    const int tid  = threadIdx.x;
    const int b    = blockIdx.y;
    const int sp   = blockIdx.x;
    const int wid  = tid >> 5;
    const int lane = tid & 31;

    const float4* base4 = reinterpret_cast<const float4*>(
        cntx + ((size_t)b * S + (size_t)sp * CH) * H);

    // thread's 4 q values (constant across tiles)
    const float4 qf = reinterpret_cast<const float4*>(g_q)[b * 256 + tid];

    float m = -1e30f, l = 0.f;
    float4 acc = make_float4(0.f, 0.f, 0.f, 0.f);

    for (int t = 0; t < NTILES; t++) {
        // load 8 rows x 4 cols into registers (8 independent LDG.128)
        float4 v[TROWS];
        #pragma unroll
        for (int s = 0; s < TROWS; s++)
            v[s] = __ldcs(&base4[(size_t)(t * TROWS + s) * 256 + tid]);

        // per-thread score partials
        float p[TROWS];
        #pragma unroll
        for (int s = 0; s < TROWS; s++) {
            float ps;
            ps = v[s].x * qf.x;
            ps = fmaf(v[s].y, qf.y, ps);
            ps = fmaf(v[s].z, qf.z, ps);
            ps = fmaf(v[s].w, qf.w, ps);
            p[s] = ps;
        }
        // warp butterfly reduce each row
        #pragma unroll
        for (int s = 0; s < TROWS; s++) {
            #pragma unroll
            for (int off = 16; off > 0; off >>= 1)
                p[s] += __shfl_xor_sync(0xffffffffu, p[s], off);
        }
        if (lane == 0) {
            #pragma unroll
            for (int s = 0; s < TROWS; s++)
                red[s * 8 + wid] = p[s];
        }
        __syncthreads();
        if (wid == 0 && lane < TROWS) {
            float sum = 0.f;
            #pragma unroll
            for (int w = 0; w < 8; w++)
                sum += red[lane * 8 + w];
            scores[lane] = sum;
        }
        __syncthreads();

        // online softmax update (all threads identical)
        float sc[TROWS];
        #pragma unroll
        for (int s = 0; s < TROWS; s++) sc[s] = scores[s];

        float mnew = m;
        #pragma unroll
        for (int s = 0; s < TROWS; s++) mnew = fmaxf(mnew, sc[s]);
        float corr = __expf(m - mnew);
        acc.x *= corr; acc.y *= corr; acc.z *= corr; acc.w *= corr;
        l *= corr;
        #pragma unroll
        for (int s = 0; s < TROWS; s++) {
            float w = __expf(sc[s] - mnew);
            l += w;
            acc.x = fmaf(w, v[s].x, acc.x);
            acc.y = fmaf(w, v[s].y, acc.y);
            acc.z = fmaf(w, v[s].z, acc.z);
            acc.w = fmaf(w, v[s].w, acc.w);
        }
        m = mnew;
        __syncthreads();   // protect red/scores for next tile
    }

    g_pacc[((size_t)b * NSPLIT + sp) * 256 + tid] = acc;
    if (tid == 0) {
        g_ml[(b * NSPLIT + sp) * 2 + 0] = m;
        g_ml[(b * NSPLIT + sp) * 2 + 1] = l;
    }
}

// ---------------------------------------------------------------------------
// Kernel 3: combine splits + epilogue. grid (8, B), 256 threads.
// chunk covers 32 float4 columns; warp g handles 2 splits; smem reduce.
// ---------------------------------------------------------------------------
__global__ __launch_bounds__(256) void combine_kernel(const float* __restrict__ h_t,
                                                      const float* __restrict__ alpha,
                                                      const float* __restrict__ beta,
                                                      float* __restrict__ out)
{
    __shared__ float4 red[8][32];

    const int tid   = threadIdx.x;
    const int lane  = tid & 31;
    const int g     = tid >> 5;            // split group 0..7
    const int chunk = blockIdx.x;          // 0..7
    const int b     = blockIdx.y;
    const int col   = chunk * 32 + lane;   // float4 column 0..255

    // global max / sum over splits (redundant per thread; g_ml is tiny/L2)
    float M = -1e30f;
    #pragma unroll
    for (int i = 0; i < NSPLIT; i++)
        M = fmaxf(M, g_ml[(b * NSPLIT + i) * 2 + 0]);
    float L = 0.f;
    #pragma unroll
    for (int i = 0; i < NSPLIT; i++) {
        float mi = g_ml[(b * NSPLIT + i) * 2 + 0];
        float li = g_ml[(b * NSPLIT + i) * 2 + 1];
        L += li * __expf(mi - M);
    }

    // this warp's 2 splits
    float4 o = make_float4(0.f, 0.f, 0.f, 0.f);
    #pragma unroll
    for (int j = 0; j < NSPLIT / 8; j++) {
        int i = g * (NSPLIT / 8) + j;
        float wi = __expf(g_ml[(b * NSPLIT + i) * 2 + 0] - M);
        float4 p = g_pacc[((size_t)b * NSPLIT + i) * 256 + col];
        o.x = fmaf(wi, p.x, o.x);
        o.y = fmaf(wi, p.y, o.y);
        o.z = fmaf(wi, p.z, o.z);
        o.w = fmaf(wi, p.w, o.w);
    }
    red[g][lane] = o;
    __syncthreads();

    if (g == 0) {
        #pragma unroll
        for (int w = 1; w < 8; w++) {
            float4 p = red[w][lane];
            o.x += p.x; o.y += p.y; o.z += p.z; o.w += p.w;
        }
        float a  = alpha[0];
        float bt = beta[0] / L;
        float4 hv = reinterpret_cast<const float4*>(h_t)[b * 256 + col];
        float4 res;
        res.x = fmaf(a, hv.x, bt * o.x);
        res.y = fmaf(a, hv.y, bt * o.y);
        res.z = fmaf(a, hv.z, bt * o.z);
        res.w = fmaf(a, hv.w, bt * o.w);
        reinterpret_cast<float4*>(out)[b * 256 + col] = res;
    }
}

// ---------------------------------------------------------------------------
extern "C" void kernel_launch(void* const* d_in, const int* in_sizes, int n_in,
                              void* d_out, int out_size)
{
    const float* h_t   = (const float*)d_in[0];
    const float* cntx  = (const float*)d_in[1];
    const float* W     = (const float*)d_in[2];
    const float* alpha = (const float*)d_in[3];
    const float* beta  = (const float*)d_in[4];
    float* out = (float*)d_out;

    qpart_kernel<<<dim3(1, KSLICES, B / BG), 256>>>(h_t, W);
    qreduce_kernel<<<B * H / 256, 256>>>();
    split_kernel<<<dim3(NSPLIT, B), 256>>>(cntx);
    combine_kernel<<<dim3(8, B), 256>>>(h_t, alpha, beta, out);
}